// round 2
// baseline (speedup 1.0000x reference)
#include <cuda_runtime.h>
#include <cuda_bf16.h>

#define MULC 256
#define BM 64          // rows per CTA
#define BN 32          // w-columns per CTA
#define KT 32          // k tile
#define TM 4           // rows per thread
#define TN 2           // w-cols per thread
#define INV_SQRT3 0.5773502691896258f

// Per (n,w) we track 8 partial contractions:
//  0: s1·W000   1: s1·W011
//  2: v1x·W110  3: v1y·W110  4: v1z·W110
//  5: v1x·W101  6: v1y·W101  7: v1z·W101
__global__ __launch_bounds__(256, 2)
void tp_fp32_kernel(const float* __restrict__ x1,
                    const float* __restrict__ x2,
                    const float* __restrict__ w000,
                    const float* __restrict__ w011,
                    const float* __restrict__ w101,
                    const float* __restrict__ w110,
                    float* __restrict__ out,
                    int n_rows)
{
    __shared__ float4 sIn[BM * KT];  // [r*KT + k] = {s1, v1x, v1y, v1z}
    __shared__ float4 sW[KT * BN];   // [k*BN + c] = {W000, W011, W110, W101}

    const int tid = threadIdx.x;
    const int tx = tid & 15;   // 0..15 -> column group
    const int ty = tid >> 4;   // 0..15 -> row group
    const int n0 = blockIdx.y * BM;
    const int w0 = blockIdx.x * BN;

    float acc[TM][TN][8];
#pragma unroll
    for (int m = 0; m < TM; m++)
#pragma unroll
        for (int cc = 0; cc < TN; cc++)
#pragma unroll
            for (int q = 0; q < 8; q++)
                acc[m][cc][q] = 0.0f;

    for (int k0 = 0; k0 < MULC; k0 += KT) {
        // ---- stage input tile: 64 rows x 32 k, deinterleave s1 / v1x/y/z ----
#pragma unroll
        for (int j = 0; j < (BM * KT) / 256; j++) {
            int p = tid + 256 * j;
            int r = p >> 5;        // p / KT
            int k = p & (KT - 1);
            int row = n0 + r;
            int rr = row < n_rows ? row : (n_rows - 1);
            const float* xr = x1 + (size_t)rr * (4 * MULC);
            int ku = k0 + k;
            float s  = xr[ku];
            float vx = xr[MULC + 3 * ku + 0];
            float vy = xr[MULC + 3 * ku + 1];
            float vz = xr[MULC + 3 * ku + 2];
            sIn[r * KT + k] = make_float4(s, vx, vy, vz);
        }
        // ---- stage weight tile: 32 k x 32 c, 4 matrices packed ----
#pragma unroll
        for (int j = 0; j < (KT * BN) / 256; j++) {
            int p = tid + 256 * j;
            int k = p >> 5;        // p / BN
            int c = p & (BN - 1);
            int idx = (k0 + k) * MULC + (w0 + c);
            sW[k * BN + c] = make_float4(w000[idx], w011[idx], w110[idx], w101[idx]);
        }
        __syncthreads();

#pragma unroll
        for (int k = 0; k < KT; k++) {
            float4 a[TM];
#pragma unroll
            for (int m = 0; m < TM; m++)
                a[m] = sIn[(ty * TM + m) * KT + k];
            float4 wv[TN];
#pragma unroll
            for (int cc = 0; cc < TN; cc++)
                wv[cc] = sW[k * BN + tx * TN + cc];
#pragma unroll
            for (int m = 0; m < TM; m++) {
#pragma unroll
                for (int cc = 0; cc < TN; cc++) {
                    float4 w = wv[cc];
                    float4 av = a[m];
                    acc[m][cc][0] = fmaf(av.x, w.x, acc[m][cc][0]);
                    acc[m][cc][1] = fmaf(av.x, w.y, acc[m][cc][1]);
                    acc[m][cc][2] = fmaf(av.y, w.z, acc[m][cc][2]);
                    acc[m][cc][3] = fmaf(av.z, w.z, acc[m][cc][3]);
                    acc[m][cc][4] = fmaf(av.w, w.z, acc[m][cc][4]);
                    acc[m][cc][5] = fmaf(av.y, w.w, acc[m][cc][5]);
                    acc[m][cc][6] = fmaf(av.z, w.w, acc[m][cc][6]);
                    acc[m][cc][7] = fmaf(av.w, w.w, acc[m][cc][7]);
                }
            }
        }
        __syncthreads();
    }

    // ---- epilogue: contract with x2 scalars, write out ----
#pragma unroll
    for (int m = 0; m < TM; m++) {
        int row = n0 + ty * TM + m;
        if (row >= n_rows) continue;
        float4 xx = *reinterpret_cast<const float4*>(x2 + (size_t)row * 4);
        // xx = {s2, v2x, v2y, v2z}
        float* orow = out + (size_t)row * (4 * MULC);
#pragma unroll
        for (int cc = 0; cc < TN; cc++) {
            int w = w0 + tx * TN + cc;
            const float* A = acc[m][cc];
            float o0 = xx.x * A[0]
                     + INV_SQRT3 * (xx.y * A[2] + xx.z * A[3] + xx.w * A[4]);
            float o1x = INV_SQRT3 * (xx.y * A[1] + xx.x * A[5]);
            float o1y = INV_SQRT3 * (xx.z * A[1] + xx.x * A[6]);
            float o1z = INV_SQRT3 * (xx.w * A[1] + xx.x * A[7]);
            orow[w] = o0;
            float* p1 = orow + MULC + 3 * w;
            p1[0] = o1x;
            p1[1] = o1y;
            p1[2] = o1z;
        }
    }
}

extern "C" void kernel_launch(void* const* d_in, const int* in_sizes, int n_in,
                              void* d_out, int out_size)
{
    const float* x1   = (const float*)d_in[0];
    const float* x2   = (const float*)d_in[1];
    const float* w000 = (const float*)d_in[2];
    const float* w011 = (const float*)d_in[3];
    const float* w101 = (const float*)d_in[4];
    const float* w110 = (const float*)d_in[5];
    float* out = (float*)d_out;

    int n_rows = in_sizes[1] / 4;   // x2 is (N, 4)

    dim3 block(256);
    dim3 grid(MULC / BN, (n_rows + BM - 1) / BM);
    tp_fp32_kernel<<<grid, block>>>(x1, x2, w000, w011, w101, w110, out, n_rows);
}

// round 4
// speedup vs baseline: 2.7357x; 2.7357x over previous
#include <cuda_runtime.h>
#include <cuda_bf16.h>
#include <cstdint>

#define MULC 256
#define KTOT 512
#define NPAD 100096            // 782 * 128 >= N=100000
#define CINV 0.57735026918962576451f

// ---------------- scratch (no cudaMalloc allowed) ----------------
__device__ __align__(128) __nv_bfloat16 g_Ah[(size_t)4 * NPAD * KTOT];   // 410 MB
__device__ __align__(128) __nv_bfloat16 g_Al[(size_t)4 * NPAD * KTOT];   // 410 MB
__device__ __align__(128) __nv_bfloat16 g_Wh[(size_t)2 * MULC * KTOT];   // Wt[mat][w][k]
__device__ __align__(128) __nv_bfloat16 g_Wl[(size_t)2 * MULC * KTOT];

__device__ __forceinline__ uint32_t smem_u32(const void* p) {
    uint32_t a;
    asm("{ .reg .u64 t; cvta.to.shared.u64 t, %1; cvt.u32.u64 %0, t; }"
        : "=r"(a) : "l"(p));
    return a;
}
__device__ __forceinline__ uint32_t sw128(uint32_t off) {
    return off ^ ((off >> 3) & 0x70u);
}

// ---------------- kernel 1: inputs -> bf16 hi/lo P matrices ----------------
// P0   = [ s1*s2     , c*(v1 . v2) ]
// P1+i = [ c*s1*v2_i , c*v1_i*s2   ]
__global__ __launch_bounds__(256) void prep_x_kernel(const float* __restrict__ x1,
                                                     const float* __restrict__ x2,
                                                     int n_rows) {
    int n = blockIdx.x;
    int k = blockIdx.y * 256 + threadIdx.x;
    float p[4] = {0.f, 0.f, 0.f, 0.f};
    if (n < n_rows) {
        const float* xr = x1 + (size_t)n * (4 * MULC);
        float s2  = x2[(size_t)n * 4 + 0];
        float w2x = x2[(size_t)n * 4 + 1];
        float w2y = x2[(size_t)n * 4 + 2];
        float w2z = x2[(size_t)n * 4 + 3];
        if (k < MULC) {
            float s = xr[k];
            p[0] = s * s2;
            p[1] = CINV * s * w2x;
            p[2] = CINV * s * w2y;
            p[3] = CINV * s * w2z;
        } else {
            int kp = k - MULC;
            float vx = xr[MULC + 3 * kp + 0];
            float vy = xr[MULC + 3 * kp + 1];
            float vz = xr[MULC + 3 * kp + 2];
            p[0] = CINV * (vx * w2x + vy * w2y + vz * w2z);
            p[1] = CINV * vx * s2;
            p[2] = CINV * vy * s2;
            p[3] = CINV * vz * s2;
        }
    }
#pragma unroll
    for (int ch = 0; ch < 4; ch++) {
        size_t idx = ((size_t)ch * NPAD + n) * KTOT + k;
        __nv_bfloat16 hi = __float2bfloat16_rn(p[ch]);
        float lo = p[ch] - __bfloat162float(hi);
        g_Ah[idx] = hi;
        g_Al[idx] = __float2bfloat16_rn(lo);
    }
}

// ---------------- kernel 2: transpose + split weights -> Wt[mat][w][k] ----------------
// mat 0 = [W000 ; W110] along k, mat 1 = [W011 ; W101]
__global__ __launch_bounds__(256) void prep_w_kernel(const float* __restrict__ w000,
                                                     const float* __restrict__ w011,
                                                     const float* __restrict__ w101,
                                                     const float* __restrict__ w110) {
    int t = blockIdx.x * 256 + threadIdx.x;     // over 2*256*512
    int mat = t >> 17;
    int rem = t & 131071;
    int w = rem >> 9;
    int k = rem & 511;
    float v;
    if (mat == 0) v = (k < MULC) ? w000[(size_t)k * MULC + w] : w110[(size_t)(k - MULC) * MULC + w];
    else          v = (k < MULC) ? w011[(size_t)k * MULC + w] : w101[(size_t)(k - MULC) * MULC + w];
    __nv_bfloat16 hi = __float2bfloat16_rn(v);
    g_Wh[t] = hi;
    g_Wl[t] = __float2bfloat16_rn(v - __bfloat162float(hi));
}

// ---------------- kernel 3: HMMA GEMM (mma.sync bf16, 3-product split) ----------------
// CTA 128 rows x 128 cols. K streamed as 24 chunks of 64 halves:
//   pass 0: Ah*Bh   pass 1: Ah*Bl   pass 2: Al*Bh  (8 chunks each)
#define KC 64                       // k (halves) per stage = 128 B rows
#define STAGES 3
#define A_BYTES (128 * 128)         // 16 KB
#define STAGE_BYTES (2 * A_BYTES)   // A + B
#define SMEM_REQ (STAGES * STAGE_BYTES)
#define TCH 24

__device__ __forceinline__ void cp16(uint32_t dst, const void* src) {
    asm volatile("cp.async.cg.shared.global [%0], [%1], 16;" :: "r"(dst), "l"(src) : "memory");
}
__device__ __forceinline__ void cp_commit() {
    asm volatile("cp.async.commit_group;" ::: "memory");
}
__device__ __forceinline__ void cp_wait1() {
    asm volatile("cp.async.wait_group 1;" ::: "memory");
}
__device__ __forceinline__ void ldsm4(uint32_t* r, uint32_t addr) {
    asm volatile("ldmatrix.sync.aligned.m8n8.x4.shared.b16 {%0,%1,%2,%3}, [%4];"
                 : "=r"(r[0]), "=r"(r[1]), "=r"(r[2]), "=r"(r[3]) : "r"(addr));
}
__device__ __forceinline__ void mma16816(float* c, const uint32_t* a, uint32_t b0, uint32_t b1) {
    asm volatile("mma.sync.aligned.m16n8k16.row.col.f32.bf16.bf16.f32 "
                 "{%0,%1,%2,%3}, {%4,%5,%6,%7}, {%8,%9}, {%0,%1,%2,%3};"
                 : "+f"(c[0]), "+f"(c[1]), "+f"(c[2]), "+f"(c[3])
                 : "r"(a[0]), "r"(a[1]), "r"(a[2]), "r"(a[3]), "r"(b0), "r"(b1));
}

__device__ __forceinline__ void load_stage(uint32_t sbase,
                                           const __nv_bfloat16* __restrict__ Aptr,
                                           const __nv_bfloat16* __restrict__ Bptr,
                                           int k0, int tid) {
#pragma unroll
    for (int it = 0; it < 4; it++) {                 // A: 128 rows x 8 chunks
        int p = tid + it * 256;
        int r = p >> 3, j = p & 7;
        cp16(sbase + sw128((uint32_t)(r * 128 + j * 16)),
             Aptr + (size_t)r * KTOT + k0 + j * 8);
    }
#pragma unroll
    for (int it = 0; it < 4; it++) {                 // B: 128 w-rows x 8 chunks
        int p = tid + it * 256;
        int r = p >> 3, j = p & 7;
        cp16(sbase + A_BYTES + sw128((uint32_t)(r * 128 + j * 16)),
             Bptr + (size_t)r * KTOT + k0 + j * 8);
    }
}

__global__ __launch_bounds__(256, 1) void tp_gemm_kernel(float* __restrict__ out, int n_rows) {
    extern __shared__ __align__(1024) char dsm[];
    const uint32_t sm0 = smem_u32(dsm);

    const int tid = threadIdx.x;
    const int lane = tid & 31;
    const int wid = tid >> 5;
    const int wm = wid & 3;            // 4 m-groups of 32 rows
    const int wn = wid >> 2;           // 2 n-groups of 64 cols

    const int ch = blockIdx.y;         // channel 0..3
    const int n0 = blockIdx.x * 128;   // row base
    const int w0 = blockIdx.z * 128;   // col base (0 or 128)

    const __nv_bfloat16* gAh = g_Ah + ((size_t)ch * NPAD + n0) * KTOT;
    const __nv_bfloat16* gAl = g_Al + ((size_t)ch * NPAD + n0) * KTOT;
    const int mat = (ch == 0) ? 0 : 1;
    const __nv_bfloat16* gWh = g_Wh + ((size_t)mat * MULC + w0) * KTOT;
    const __nv_bfloat16* gWl = g_Wl + ((size_t)mat * MULC + w0) * KTOT;

    float acc[2][8][4];
#pragma unroll
    for (int mf = 0; mf < 2; mf++)
#pragma unroll
        for (int nf = 0; nf < 8; nf++)
#pragma unroll
            for (int q = 0; q < 4; q++)
                acc[mf][nf][q] = 0.0f;

    // chunk t -> pass, k0, pointers
    auto A_of = [&](int t) { return (t < 16) ? gAh : gAl; };
    auto B_of = [&](int t) { return (t >= 8 && t < 16) ? gWl : gWh; };
    auto K_of = [&](int t) { return (t & 7) * KC; };

    // prologue: stages 0,1
    load_stage(sm0, A_of(0), B_of(0), K_of(0), tid);
    cp_commit();
    load_stage(sm0 + STAGE_BYTES, A_of(1), B_of(1), K_of(1), tid);
    cp_commit();

    // ldmatrix lane addressing (constant per thread)
    const int a_row = (lane & 15);
    const int a_col = (lane >> 4) << 3;
    const int b_row = (lane & 7) + ((lane >> 4) << 3);
    const int b_col = ((lane >> 3) & 1) << 3;

    for (int t = 0; t < TCH; t++) {
        cp_wait1();
        __syncthreads();
        const uint32_t sA = sm0 + (t % STAGES) * STAGE_BYTES;
        const uint32_t sB = sA + A_BYTES;

#pragma unroll
        for (int kk = 0; kk < KC; kk += 16) {
            uint32_t a[2][4];
#pragma unroll
            for (int mf = 0; mf < 2; mf++) {
                int row = wm * 32 + mf * 16 + a_row;
                int col = kk + a_col;
                ldsm4(a[mf], sA + sw128((uint32_t)(row * 128 + col * 2)));
            }
#pragma unroll
            for (int bi = 0; bi < 4; bi++) {
                uint32_t b[4];
                int row = wn * 64 + bi * 16 + b_row;
                int col = kk + b_col;
                ldsm4(b, sB + sw128((uint32_t)(row * 128 + col * 2)));
#pragma unroll
                for (int mf = 0; mf < 2; mf++) {
                    mma16816(acc[mf][bi * 2 + 0], a[mf], b[0], b[1]);
                    mma16816(acc[mf][bi * 2 + 1], a[mf], b[2], b[3]);
                }
            }
        }

        int tn = t + STAGES - 1;
        if (tn < TCH) {
            load_stage(sm0 + (tn % STAGES) * STAGE_BYTES, A_of(tn), B_of(tn), K_of(tn), tid);
        }
        cp_commit();   // keep group count uniform even when no loads issued
    }

    // ---------------- epilogue ----------------
    const int rbase = n0 + wm * 32 + (lane >> 2);
    const int cb0 = w0 + wn * 64 + 2 * (lane & 3);
#pragma unroll
    for (int mf = 0; mf < 2; mf++) {
#pragma unroll
        for (int nf = 0; nf < 8; nf++) {
            int c = cb0 + nf * 8;
            float* A = acc[mf][nf];
#pragma unroll
            for (int h = 0; h < 2; h++) {           // h=0 -> row, h=1 -> row+8
                int row = rbase + mf * 16 + h * 8;
                if (row >= n_rows) continue;
                float* orow = out + (size_t)row * (4 * MULC);
                float v0 = A[2 * h + 0], v1 = A[2 * h + 1];
                if (ch == 0) {
                    *(float2*)(orow + c) = make_float2(v0, v1);
                } else {
                    float* p1 = orow + MULC + (ch - 1);
                    p1[3 * c] = v0;
                    p1[3 * (c + 1)] = v1;
                }
            }
        }
    }
}

// ---------------- launch ----------------
extern "C" void kernel_launch(void* const* d_in, const int* in_sizes, int n_in,
                              void* d_out, int out_size) {
    const float* x1   = (const float*)d_in[0];
    const float* x2   = (const float*)d_in[1];
    const float* w000 = (const float*)d_in[2];
    const float* w011 = (const float*)d_in[3];
    const float* w101 = (const float*)d_in[4];
    const float* w110 = (const float*)d_in[5];
    float* out = (float*)d_out;

    int n_rows = in_sizes[1] / 4;
    int row_tiles = (n_rows + 127) / 128;
    if (row_tiles * 128 > NPAD) row_tiles = NPAD / 128;

    prep_w_kernel<<<(2 * MULC * KTOT) / 256, 256>>>(w000, w011, w101, w110);
    prep_x_kernel<<<dim3(row_tiles * 128, 2), 256>>>(x1, x2, n_rows);

    cudaFuncSetAttribute(tp_gemm_kernel, cudaFuncAttributeMaxDynamicSharedMemorySize, SMEM_REQ);
    tp_gemm_kernel<<<dim3(row_tiles, 4, 2), 256, SMEM_REQ>>>(out, n_rows);
}

// round 5
// speedup vs baseline: 4.3395x; 1.5863x over previous
#include <cuda_runtime.h>
#include <cuda_fp16.h>
#include <cstdint>

#define MULC 256
#define KTOT 512
#define NPAD 100096            // 782 * 128 >= N=100000
#define CINV 0.57735026918962576451f

// ---------------- scratch (no cudaMalloc allowed) ----------------
__device__ __align__(128) __half g_Ah[(size_t)4 * NPAD * KTOT];   // 410 MB
__device__ __align__(128) __half g_Wh[(size_t)2 * MULC * KTOT];   // Wt[mat][w][k] hi
__device__ __align__(128) __half g_Wl[(size_t)2 * MULC * KTOT];   // lo

__device__ __forceinline__ uint32_t smem_u32(const void* p) {
    uint32_t a;
    asm("{ .reg .u64 t; cvta.to.shared.u64 t, %1; cvt.u32.u64 %0, t; }"
        : "=r"(a) : "l"(p));
    return a;
}
__device__ __forceinline__ uint32_t sw128(uint32_t off) {
    return off ^ ((off >> 3) & 0x70u);
}

// ---------------- kernel 1: inputs -> fp16 P matrices ----------------
// P0   = [ s1*s2     , c*(v1 . v2) ]
// P1+i = [ c*s1*v2_i , c*v1_i*s2   ]
__global__ __launch_bounds__(256) void prep_x_kernel(const float* __restrict__ x1,
                                                     const float* __restrict__ x2,
                                                     int n_rows) {
    int n = blockIdx.x;
    int k = blockIdx.y * 256 + threadIdx.x;
    float p[4] = {0.f, 0.f, 0.f, 0.f};
    if (n < n_rows) {
        const float* xr = x1 + (size_t)n * (4 * MULC);
        float s2  = x2[(size_t)n * 4 + 0];
        float w2x = x2[(size_t)n * 4 + 1];
        float w2y = x2[(size_t)n * 4 + 2];
        float w2z = x2[(size_t)n * 4 + 3];
        if (k < MULC) {
            float s = xr[k];
            p[0] = s * s2;
            p[1] = CINV * s * w2x;
            p[2] = CINV * s * w2y;
            p[3] = CINV * s * w2z;
        } else {
            int kp = k - MULC;
            float vx = xr[MULC + 3 * kp + 0];
            float vy = xr[MULC + 3 * kp + 1];
            float vz = xr[MULC + 3 * kp + 2];
            p[0] = CINV * (vx * w2x + vy * w2y + vz * w2z);
            p[1] = CINV * vx * s2;
            p[2] = CINV * vy * s2;
            p[3] = CINV * vz * s2;
        }
    }
#pragma unroll
    for (int ch = 0; ch < 4; ch++) {
        size_t idx = ((size_t)ch * NPAD + n) * KTOT + k;
        g_Ah[idx] = __float2half_rn(p[ch]);
    }
}

// ---------------- kernel 2: transpose + split weights (fp16 hi/lo) ----------------
// mat 0 = [W000 ; W110] along k, mat 1 = [W011 ; W101]
__global__ __launch_bounds__(256) void prep_w_kernel(const float* __restrict__ w000,
                                                     const float* __restrict__ w011,
                                                     const float* __restrict__ w101,
                                                     const float* __restrict__ w110) {
    int t = blockIdx.x * 256 + threadIdx.x;     // over 2*256*512
    int mat = t >> 17;
    int rem = t & 131071;
    int w = rem >> 9;
    int k = rem & 511;
    float v;
    if (mat == 0) v = (k < MULC) ? w000[(size_t)k * MULC + w] : w110[(size_t)(k - MULC) * MULC + w];
    else          v = (k < MULC) ? w011[(size_t)k * MULC + w] : w101[(size_t)(k - MULC) * MULC + w];
    __half hi = __float2half_rn(v);
    g_Wh[t] = hi;
    g_Wl[t] = __float2half_rn(v - __half2float(hi));
}

// ---------------- kernel 3: HMMA GEMM (mma.sync fp16, Ah*(Bh+Bl)) ----------------
// CTA 128 rows x 256 cols (full MULC). K=512 in 8 chunks of 64. 2-stage cp.async.
#define KC 64
#define NCH 8
#define A_BYTES (128 * 128)             // 16 KB
#define BH_OFF  A_BYTES                 // 32 KB (256 w-rows x 128B)
#define BL_OFF  (A_BYTES + 32 * 1024)
#define STAGE_BYTES (A_BYTES + 64 * 1024)   // 80 KB
#define SMEM_REQ (2 * STAGE_BYTES)          // 160 KB

__device__ __forceinline__ void cp16(uint32_t dst, const void* src) {
    asm volatile("cp.async.cg.shared.global [%0], [%1], 16;" :: "r"(dst), "l"(src) : "memory");
}
__device__ __forceinline__ void cp_commit() {
    asm volatile("cp.async.commit_group;" ::: "memory");
}
__device__ __forceinline__ void cp_wait1() {
    asm volatile("cp.async.wait_group 1;" ::: "memory");
}
__device__ __forceinline__ void ldsm4(uint32_t* r, uint32_t addr) {
    asm volatile("ldmatrix.sync.aligned.m8n8.x4.shared.b16 {%0,%1,%2,%3}, [%4];"
                 : "=r"(r[0]), "=r"(r[1]), "=r"(r[2]), "=r"(r[3]) : "r"(addr));
}
__device__ __forceinline__ void mma16816(float* c, const uint32_t* a, uint32_t b0, uint32_t b1) {
    asm volatile("mma.sync.aligned.m16n8k16.row.col.f32.f16.f16.f32 "
                 "{%0,%1,%2,%3}, {%4,%5,%6,%7}, {%8,%9}, {%0,%1,%2,%3};"
                 : "+f"(c[0]), "+f"(c[1]), "+f"(c[2]), "+f"(c[3])
                 : "r"(a[0]), "r"(a[1]), "r"(a[2]), "r"(a[3]), "r"(b0), "r"(b1));
}

__device__ __forceinline__ void load_stage(uint32_t sbase,
                                           const __half* __restrict__ Aptr,
                                           const __half* __restrict__ Whp,
                                           const __half* __restrict__ Wlp,
                                           int k0, int tid) {
#pragma unroll
    for (int it = 0; it < 4; it++) {                 // A: 128 rows x 8 x 16B
        int p = tid + it * 256;
        int r = p >> 3, j = p & 7;
        cp16(sbase + sw128((uint32_t)(r * 128 + j * 16)),
             Aptr + (size_t)r * KTOT + k0 + j * 8);
    }
#pragma unroll
    for (int it = 0; it < 8; it++) {                 // Bh: 256 w-rows
        int p = tid + it * 256;
        int r = p >> 3, j = p & 7;
        cp16(sbase + BH_OFF + sw128((uint32_t)(r * 128 + j * 16)),
             Whp + (size_t)r * KTOT + k0 + j * 8);
    }
#pragma unroll
    for (int it = 0; it < 8; it++) {                 // Bl: 256 w-rows
        int p = tid + it * 256;
        int r = p >> 3, j = p & 7;
        cp16(sbase + BL_OFF + sw128((uint32_t)(r * 128 + j * 16)),
             Wlp + (size_t)r * KTOT + k0 + j * 8);
    }
}

__global__ __launch_bounds__(256, 1) void tp_gemm_kernel(float* __restrict__ out, int n_rows) {
    extern __shared__ __align__(1024) char dsm[];
    const uint32_t sm0 = smem_u32(dsm);

    const int tid = threadIdx.x;
    const int lane = tid & 31;
    const int wid = tid >> 5;
    const int wm = wid >> 2;           // 2 m-groups of 64 rows
    const int wn = wid & 3;            // 4 n-groups of 64 cols

    const int ch = blockIdx.y;         // channel 0..3
    const int n0 = blockIdx.x * 128;   // row base

    const __half* gAh = g_Ah + ((size_t)ch * NPAD + n0) * KTOT;
    const int mat = (ch == 0) ? 0 : 1;
    const __half* gWh = g_Wh + (size_t)mat * MULC * KTOT;
    const __half* gWl = g_Wl + (size_t)mat * MULC * KTOT;

    float acc[4][8][4];
#pragma unroll
    for (int mf = 0; mf < 4; mf++)
#pragma unroll
        for (int nf = 0; nf < 8; nf++)
#pragma unroll
            for (int q = 0; q < 4; q++)
                acc[mf][nf][q] = 0.0f;

    // prologue: stages 0,1
    load_stage(sm0, gAh, gWh, gWl, 0, tid);
    cp_commit();
    load_stage(sm0 + STAGE_BYTES, gAh, gWh, gWl, KC, tid);
    cp_commit();

    const int a_row = (lane & 15);
    const int a_col = (lane >> 4) << 3;
    const int b_row = (lane & 7) + ((lane >> 4) << 3);
    const int b_col = ((lane >> 3) & 1) << 3;

    for (int t = 0; t < NCH; t++) {
        cp_wait1();
        __syncthreads();
        const uint32_t sA = sm0 + (t & 1) * STAGE_BYTES;

#pragma unroll
        for (int kk = 0; kk < KC; kk += 16) {
            uint32_t a[4][4];
#pragma unroll
            for (int mf = 0; mf < 4; mf++) {
                int row = wm * 64 + mf * 16 + a_row;
                ldsm4(a[mf], sA + sw128((uint32_t)(row * 128 + (kk + a_col) * 2)));
            }
#pragma unroll
            for (int bi = 0; bi < 4; bi++) {
                int rowb = wn * 64 + bi * 16 + b_row;
                uint32_t boff = sw128((uint32_t)(rowb * 128 + (kk + b_col) * 2));
                uint32_t bh[4], bl[4];
                ldsm4(bh, sA + BH_OFF + boff);
                ldsm4(bl, sA + BL_OFF + boff);
#pragma unroll
                for (int mf = 0; mf < 4; mf++) {
                    mma16816(acc[mf][bi * 2 + 0], a[mf], bh[0], bh[1]);
                    mma16816(acc[mf][bi * 2 + 1], a[mf], bh[2], bh[3]);
                }
#pragma unroll
                for (int mf = 0; mf < 4; mf++) {
                    mma16816(acc[mf][bi * 2 + 0], a[mf], bl[0], bl[1]);
                    mma16816(acc[mf][bi * 2 + 1], a[mf], bl[2], bl[3]);
                }
            }
        }
        __syncthreads();

        int tn = t + 2;
        if (tn < NCH) {
            load_stage(sm0 + (tn & 1) * STAGE_BYTES, gAh, gWh, gWl, tn * KC, tid);
        }
        cp_commit();   // uniform group count
    }

    // ---------------- epilogue ----------------
    const int rb = n0 + wm * 64 + (lane >> 2);
    const int cb0 = wn * 64 + 2 * (lane & 3);
#pragma unroll
    for (int mf = 0; mf < 4; mf++) {
#pragma unroll
        for (int nf = 0; nf < 8; nf++) {
            int c = cb0 + nf * 8;
            float* A = acc[mf][nf];
#pragma unroll
            for (int h = 0; h < 2; h++) {
                int row = rb + mf * 16 + h * 8;
                if (row >= n_rows) continue;
                float* orow = out + (size_t)row * (4 * MULC);
                float v0 = A[2 * h + 0], v1 = A[2 * h + 1];
                if (ch == 0) {
                    *(float2*)(orow + c) = make_float2(v0, v1);
                } else {
                    float* p1 = orow + MULC + (ch - 1);
                    p1[3 * c] = v0;
                    p1[3 * (c + 1)] = v1;
                }
            }
        }
    }
}

// ---------------- launch ----------------
extern "C" void kernel_launch(void* const* d_in, const int* in_sizes, int n_in,
                              void* d_out, int out_size) {
    const float* x1   = (const float*)d_in[0];
    const float* x2   = (const float*)d_in[1];
    const float* w000 = (const float*)d_in[2];
    const float* w011 = (const float*)d_in[3];
    const float* w101 = (const float*)d_in[4];
    const float* w110 = (const float*)d_in[5];
    float* out = (float*)d_out;

    int n_rows = in_sizes[1] / 4;
    int row_tiles = (n_rows + 127) / 128;
    if (row_tiles * 128 > NPAD) row_tiles = NPAD / 128;

    prep_w_kernel<<<(2 * MULC * KTOT) / 256, 256>>>(w000, w011, w101, w110);
    prep_x_kernel<<<dim3(row_tiles * 128, 2), 256>>>(x1, x2, n_rows);

    cudaFuncSetAttribute(tp_gemm_kernel, cudaFuncAttributeMaxDynamicSharedMemorySize, SMEM_REQ);
    tp_gemm_kernel<<<dim3(row_tiles, 4), 256, SMEM_REQ>>>(out, n_rows);
}

// round 7
// speedup vs baseline: 5.1777x; 1.1932x over previous
#include <cuda_runtime.h>
#include <cuda_fp16.h>
#include <cstdint>

#define MULC 256
#define KTOT 512
#define NPAD 100096            // 782 * 128 >= N=100000
#define CINV 0.57735026918962576451f

// ---------------- scratch (no cudaMalloc allowed) ----------------
__device__ __align__(128) __half g_Ah[(size_t)4 * NPAD * KTOT];   // 410 MB
__device__ __align__(128) __half g_Wh[(size_t)2 * MULC * KTOT];   // Wt[mat][w][k]

__device__ __forceinline__ uint32_t smem_u32(const void* p) {
    uint32_t a;
    asm("{ .reg .u64 t; cvta.to.shared.u64 t, %1; cvt.u32.u64 %0, t; }"
        : "=r"(a) : "l"(p));
    return a;
}
__device__ __forceinline__ uint32_t sw128(uint32_t off) {
    return off ^ ((off >> 3) & 0x70u);
}

// ---------------- kernel 1: inputs -> fp16 P matrices ----------------
// P0   = [ s1*s2     , c*(v1 . v2) ]
// P1+i = [ c*s1*v2_i , c*v1_i*s2   ]
__global__ __launch_bounds__(256) void prep_x_kernel(const float* __restrict__ x1,
                                                     const float* __restrict__ x2,
                                                     int n_rows) {
    int n = blockIdx.x;
    int k = blockIdx.y * 256 + threadIdx.x;
    float p[4] = {0.f, 0.f, 0.f, 0.f};
    if (n < n_rows) {
        const float* xr = x1 + (size_t)n * (4 * MULC);
        float s2  = x2[(size_t)n * 4 + 0];
        float w2x = x2[(size_t)n * 4 + 1];
        float w2y = x2[(size_t)n * 4 + 2];
        float w2z = x2[(size_t)n * 4 + 3];
        if (k < MULC) {
            float s = xr[k];
            p[0] = s * s2;
            p[1] = CINV * s * w2x;
            p[2] = CINV * s * w2y;
            p[3] = CINV * s * w2z;
        } else {
            int kp = k - MULC;
            float vx = xr[MULC + 3 * kp + 0];
            float vy = xr[MULC + 3 * kp + 1];
            float vz = xr[MULC + 3 * kp + 2];
            p[0] = CINV * (vx * w2x + vy * w2y + vz * w2z);
            p[1] = CINV * vx * s2;
            p[2] = CINV * vy * s2;
            p[3] = CINV * vz * s2;
        }
    }
#pragma unroll
    for (int ch = 0; ch < 4; ch++) {
        size_t idx = ((size_t)ch * NPAD + n) * KTOT + k;
        g_Ah[idx] = __float2half_rn(p[ch]);
    }
}

// ---------------- kernel 2: transpose weights -> fp16 Wt[mat][w][k] ----------------
// mat 0 = [W000 ; W110] along k, mat 1 = [W011 ; W101]
__global__ __launch_bounds__(256) void prep_w_kernel(const float* __restrict__ w000,
                                                     const float* __restrict__ w011,
                                                     const float* __restrict__ w101,
                                                     const float* __restrict__ w110) {
    int t = blockIdx.x * 256 + threadIdx.x;     // over 2*256*512
    int mat = t >> 17;
    int rem = t & 131071;
    int w = rem >> 9;
    int k = rem & 511;
    float v;
    if (mat == 0) v = (k < MULC) ? w000[(size_t)k * MULC + w] : w110[(size_t)(k - MULC) * MULC + w];
    else          v = (k < MULC) ? w011[(size_t)k * MULC + w] : w101[(size_t)(k - MULC) * MULC + w];
    g_Wh[t] = __float2half_rn(v);
}

// ---------------- kernel 3: HMMA GEMM (mma.sync fp16, single product) ----------------
// CTA 128 rows x 256 cols. K=512 in 8 chunks of 64. 3-stage cp.async pipeline.
#define KC 64
#define NCH 8
#define A_BYTES (128 * 128)             // 16 KB
#define B_OFF   A_BYTES                 // B: 256 w-rows x 128B = 32 KB
#define STAGE_BYTES (A_BYTES + 32 * 1024)   // 48 KB
#define STAGES 3
#define SMEM_REQ (STAGES * STAGE_BYTES)     // 144 KB

__device__ __forceinline__ void cp16(uint32_t dst, const void* src) {
    asm volatile("cp.async.cg.shared.global [%0], [%1], 16;" :: "r"(dst), "l"(src) : "memory");
}
__device__ __forceinline__ void cp_commit() {
    asm volatile("cp.async.commit_group;" ::: "memory");
}
__device__ __forceinline__ void cp_wait2() {
    asm volatile("cp.async.wait_group 2;" ::: "memory");
}
__device__ __forceinline__ void ldsm4(uint32_t* r, uint32_t addr) {
    asm volatile("ldmatrix.sync.aligned.m8n8.x4.shared.b16 {%0,%1,%2,%3}, [%4];"
                 : "=r"(r[0]), "=r"(r[1]), "=r"(r[2]), "=r"(r[3]) : "r"(addr));
}
__device__ __forceinline__ void mma16816(float* c, const uint32_t* a, uint32_t b0, uint32_t b1) {
    asm volatile("mma.sync.aligned.m16n8k16.row.col.f32.f16.f16.f32 "
                 "{%0,%1,%2,%3}, {%4,%5,%6,%7}, {%8,%9}, {%0,%1,%2,%3};"
                 : "+f"(c[0]), "+f"(c[1]), "+f"(c[2]), "+f"(c[3])
                 : "r"(a[0]), "r"(a[1]), "r"(a[2]), "r"(a[3]), "r"(b0), "r"(b1));
}

__device__ __forceinline__ void load_stage(uint32_t sbase,
                                           const __half* __restrict__ Aptr,
                                           const __half* __restrict__ Wp,
                                           int k0, int tid) {
#pragma unroll
    for (int it = 0; it < 4; it++) {                 // A: 128 rows x 8 x 16B
        int p = tid + it * 256;
        int r = p >> 3, j = p & 7;
        cp16(sbase + sw128((uint32_t)(r * 128 + j * 16)),
             Aptr + (size_t)r * KTOT + k0 + j * 8);
    }
#pragma unroll
    for (int it = 0; it < 8; it++) {                 // B: 256 w-rows
        int p = tid + it * 256;
        int r = p >> 3, j = p & 7;
        cp16(sbase + B_OFF + sw128((uint32_t)(r * 128 + j * 16)),
             Wp + (size_t)r * KTOT + k0 + j * 8);
    }
}

__global__ __launch_bounds__(256, 1) void tp_gemm_kernel(float* __restrict__ out, int n_rows) {
    extern __shared__ __align__(1024) char dsm[];
    const uint32_t sm0 = smem_u32(dsm);

    const int tid = threadIdx.x;
    const int lane = tid & 31;
    const int wid = tid >> 5;
    const int wm = wid >> 2;           // 2 m-groups of 64 rows
    const int wn = wid & 3;            // 4 n-groups of 64 cols

    const int ch = blockIdx.y;         // channel 0..3
    const int n0 = blockIdx.x * 128;   // row base

    const __half* gAh = g_Ah + ((size_t)ch * NPAD + n0) * KTOT;
    const int mat = (ch == 0) ? 0 : 1;
    const __half* gWh = g_Wh + (size_t)mat * MULC * KTOT;

    float acc[4][8][4];
#pragma unroll
    for (int mf = 0; mf < 4; mf++)
#pragma unroll
        for (int nf = 0; nf < 8; nf++)
#pragma unroll
            for (int q = 0; q < 4; q++)
                acc[mf][nf][q] = 0.0f;

    // prologue: stages 0,1
    load_stage(sm0, gAh, gWh, 0, tid);
    cp_commit();
    load_stage(sm0 + STAGE_BYTES, gAh, gWh, KC, tid);
    cp_commit();

    const int a_row = (lane & 15);
    const int a_col = (lane >> 4) << 3;
    const int b_row = (lane & 7) + ((lane >> 4) << 3);
    const int b_col = ((lane >> 3) & 1) << 3;

    for (int t = 0; t < NCH; t++) {
        // prefetch t+2 into the buffer freed by t-1 (safe: synced last iter)
        int tn = t + 2;
        if (tn < NCH) {
            load_stage(sm0 + (tn % STAGES) * STAGE_BYTES, gAh, gWh, tn * KC, tid);
        }
        cp_commit();               // uniform group count
        cp_wait2();                // stage t complete
        __syncthreads();

        const uint32_t sA = sm0 + (t % STAGES) * STAGE_BYTES;

#pragma unroll
        for (int kk = 0; kk < KC; kk += 16) {
            uint32_t a[4][4];
#pragma unroll
            for (int mf = 0; mf < 4; mf++) {
                int row = wm * 64 + mf * 16 + a_row;
                ldsm4(a[mf], sA + sw128((uint32_t)(row * 128 + (kk + a_col) * 2)));
            }
#pragma unroll
            for (int bi = 0; bi < 4; bi++) {
                int rowb = wn * 64 + bi * 16 + b_row;
                uint32_t bfrag[4];
                ldsm4(bfrag, sA + B_OFF + sw128((uint32_t)(rowb * 128 + (kk + b_col) * 2)));
#pragma unroll
                for (int mf = 0; mf < 4; mf++) {
                    mma16816(acc[mf][bi * 2 + 0], a[mf], bfrag[0], bfrag[1]);
                    mma16816(acc[mf][bi * 2 + 1], a[mf], bfrag[2], bfrag[3]);
                }
            }
        }
        __syncthreads();
    }

    // ---------------- epilogue ----------------
    const int rb = n0 + wm * 64 + (lane >> 2);
    const int cb0 = wn * 64 + 2 * (lane & 3);
#pragma unroll
    for (int mf = 0; mf < 4; mf++) {
#pragma unroll
        for (int nf = 0; nf < 8; nf++) {
            int c = cb0 + nf * 8;
            float* A = acc[mf][nf];
#pragma unroll
            for (int h = 0; h < 2; h++) {
                int row = rb + mf * 16 + h * 8;
                if (row >= n_rows) continue;
                float* orow = out + (size_t)row * (4 * MULC);
                float v0 = A[2 * h + 0], v1 = A[2 * h + 1];
                if (ch == 0) {
                    *(float2*)(orow + c) = make_float2(v0, v1);
                } else {
                    float* p1 = orow + MULC + (ch - 1);
                    p1[3 * c] = v0;
                    p1[3 * (c + 1)] = v1;
                }
            }
        }
    }
}

// ---------------- launch ----------------
extern "C" void kernel_launch(void* const* d_in, const int* in_sizes, int n_in,
                              void* d_out, int out_size) {
    const float* x1   = (const float*)d_in[0];
    const float* x2   = (const float*)d_in[1];
    const float* w000 = (const float*)d_in[2];
    const float* w011 = (const float*)d_in[3];
    const float* w101 = (const float*)d_in[4];
    const float* w110 = (const float*)d_in[5];
    float* out = (float*)d_out;

    int n_rows = in_sizes[1] / 4;
    int row_tiles = (n_rows + 127) / 128;
    if (row_tiles * 128 > NPAD) row_tiles = NPAD / 128;

    prep_w_kernel<<<(2 * MULC * KTOT) / 256, 256>>>(w000, w011, w101, w110);
    prep_x_kernel<<<dim3(row_tiles * 128, 2), 256>>>(x1, x2, n_rows);

    cudaFuncSetAttribute(tp_gemm_kernel, cudaFuncAttributeMaxDynamicSharedMemorySize, SMEM_REQ);
    tp_gemm_kernel<<<dim3(row_tiles, 4), 256, SMEM_REQ>>>(out, n_rows);
}

// round 8
// speedup vs baseline: 6.5355x; 1.2622x over previous
#include <cuda_runtime.h>
#include <cuda_fp16.h>
#include <cstdint>

#define MULC 256
#define KTOT 512
#define NPAD 100096            // >= N=100000
#define CINV 0.57735026918962576451f

// ---------------- scratch (no cudaMalloc allowed) ----------------
__device__ __align__(128) __half g_Ah[(size_t)4 * NPAD * KTOT];   // 410 MB
__device__ __align__(128) __half g_Wh[(size_t)2 * MULC * KTOT];   // Wt[mat][w][k]

__device__ __forceinline__ uint32_t smem_u32(const void* p) {
    uint32_t a;
    asm("{ .reg .u64 t; cvta.to.shared.u64 t, %1; cvt.u32.u64 %0, t; }"
        : "=r"(a) : "l"(p));
    return a;
}
__device__ __forceinline__ uint32_t sw128(uint32_t off) {
    return off ^ ((off >> 3) & 0x70u);
}

// ---------------- kernel 1: inputs -> fp16 P matrices ----------------
// P0   = [ s1*s2     , c*(v1 . v2) ]
// P1+i = [ c*s1*v2_i , c*v1_i*s2   ]
__global__ __launch_bounds__(256) void prep_x_kernel(const float* __restrict__ x1,
                                                     const float* __restrict__ x2,
                                                     int n_rows) {
    int n = blockIdx.x;
    int k = blockIdx.y * 256 + threadIdx.x;
    float p[4] = {0.f, 0.f, 0.f, 0.f};
    if (n < n_rows) {
        const float* xr = x1 + (size_t)n * (4 * MULC);
        float s2  = x2[(size_t)n * 4 + 0];
        float w2x = x2[(size_t)n * 4 + 1];
        float w2y = x2[(size_t)n * 4 + 2];
        float w2z = x2[(size_t)n * 4 + 3];
        if (k < MULC) {
            float s = xr[k];
            p[0] = s * s2;
            p[1] = CINV * s * w2x;
            p[2] = CINV * s * w2y;
            p[3] = CINV * s * w2z;
        } else {
            int kp = k - MULC;
            float vx = xr[MULC + 3 * kp + 0];
            float vy = xr[MULC + 3 * kp + 1];
            float vz = xr[MULC + 3 * kp + 2];
            p[0] = CINV * (vx * w2x + vy * w2y + vz * w2z);
            p[1] = CINV * vx * s2;
            p[2] = CINV * vy * s2;
            p[3] = CINV * vz * s2;
        }
    }
#pragma unroll
    for (int ch = 0; ch < 4; ch++) {
        size_t idx = ((size_t)ch * NPAD + n) * KTOT + k;
        g_Ah[idx] = __float2half_rn(p[ch]);
    }
}

// ---------------- kernel 2: transpose weights -> fp16 Wt[mat][w][k] ----------------
// mat 0 = [W000 ; W110] along k, mat 1 = [W011 ; W101]
__global__ __launch_bounds__(256) void prep_w_kernel(const float* __restrict__ w000,
                                                     const float* __restrict__ w011,
                                                     const float* __restrict__ w101,
                                                     const float* __restrict__ w110) {
    int t = blockIdx.x * 256 + threadIdx.x;     // over 2*256*512
    int mat = t >> 17;
    int rem = t & 131071;
    int w = rem >> 9;
    int k = rem & 511;
    float v;
    if (mat == 0) v = (k < MULC) ? w000[(size_t)k * MULC + w] : w110[(size_t)(k - MULC) * MULC + w];
    else          v = (k < MULC) ? w011[(size_t)k * MULC + w] : w101[(size_t)(k - MULC) * MULC + w];
    g_Wh[t] = __float2half_rn(v);
}

// ---------------- kernel 3: HMMA GEMM, all 4 channels per CTA ----------------
// CTA: 32 rows x 256 cols x 4 channels. K=512 in 8 chunks of 64, 2-stage cp.async.
#define KC 64
#define NCH 8
#define ROWS_CTA 32
#define A_BYTES (4 * ROWS_CTA * 128)        // 16 KB  (4 channel A tiles)
#define B_OFF   A_BYTES
#define B_BYTES (512 * 128)                 // 64 KB  (both weight mats' k-slice)
#define STAGE_BYTES (A_BYTES + B_BYTES)     // 80 KB
#define SMEM_REQ (2 * STAGE_BYTES)          // 160 KB (also covers 128 KB epilogue tile)

__device__ __forceinline__ void cp16(uint32_t dst, const void* src) {
    asm volatile("cp.async.cg.shared.global [%0], [%1], 16;" :: "r"(dst), "l"(src) : "memory");
}
__device__ __forceinline__ void cp_commit() {
    asm volatile("cp.async.commit_group;" ::: "memory");
}
__device__ __forceinline__ void cp_wait1() {
    asm volatile("cp.async.wait_group 1;" ::: "memory");
}
__device__ __forceinline__ void ldsm4(uint32_t* r, uint32_t addr) {
    asm volatile("ldmatrix.sync.aligned.m8n8.x4.shared.b16 {%0,%1,%2,%3}, [%4];"
                 : "=r"(r[0]), "=r"(r[1]), "=r"(r[2]), "=r"(r[3]) : "r"(addr));
}
__device__ __forceinline__ void mma16816(float* c, const uint32_t* a, uint32_t b0, uint32_t b1) {
    asm volatile("mma.sync.aligned.m16n8k16.row.col.f32.f16.f16.f32 "
                 "{%0,%1,%2,%3}, {%4,%5,%6,%7}, {%8,%9}, {%0,%1,%2,%3};"
                 : "+f"(c[0]), "+f"(c[1]), "+f"(c[2]), "+f"(c[3])
                 : "r"(a[0]), "r"(a[1]), "r"(a[2]), "r"(a[3]), "r"(b0), "r"(b1));
}

__device__ __forceinline__ void load_stage(uint32_t sbase, int n0, int k0,
                                           int tid, int n_rows) {
    // A: 4 channels x 32 rows x 128B  (1024 x 16B units, 4 per thread)
#pragma unroll
    for (int it = 0; it < 4; it++) {
        int p = tid + it * 256;
        int r = p >> 3, j = p & 7;          // r: 0..127 -> ch = r>>5, row = r&31
        int ch = r >> 5;
        int row = n0 + (r & 31);
        if (row >= n_rows) row = n_rows - 1;
        cp16(sbase + sw128((uint32_t)(r * 128 + j * 16)),
             g_Ah + ((size_t)ch * NPAD + row) * KTOT + k0 + j * 8);
    }
    // B: both mats, 512 w-rows x 128B  (4096 x 16B units, 16 per thread)
#pragma unroll
    for (int it = 0; it < 16; it++) {
        int p = tid + it * 256;
        int r = p >> 3, j = p & 7;          // r: 0..511 spans mat0 then mat1
        cp16(sbase + B_OFF + sw128((uint32_t)(r * 128 + j * 16)),
             g_Wh + (size_t)r * KTOT + k0 + j * 8);
    }
}

__global__ __launch_bounds__(256, 1) void tp_gemm_kernel(float* __restrict__ out, int n_rows) {
    extern __shared__ __align__(1024) char dsm[];
    const uint32_t sm0 = smem_u32(dsm);

    const int tid = threadIdx.x;
    const int lane = tid & 31;
    const int wid = tid >> 5;
    const int ch = wid >> 1;            // channel 0..3
    const int colh = (wid & 1) * 128;   // col half within 256
    const int matsel = (ch == 0) ? 0 : 1;
    const int n0 = blockIdx.x * ROWS_CTA;

    float acc[2][16][4];
#pragma unroll
    for (int mf = 0; mf < 2; mf++)
#pragma unroll
        for (int nf = 0; nf < 16; nf++)
#pragma unroll
            for (int q = 0; q < 4; q++)
                acc[mf][nf][q] = 0.0f;

    load_stage(sm0, n0, 0, tid, n_rows);
    cp_commit();
    load_stage(sm0 + STAGE_BYTES, n0, KC, tid, n_rows);
    cp_commit();

    const int a_row = (lane & 15);
    const int a_col = (lane >> 4) << 3;
    const int b_row = (lane & 7) + ((lane >> 4) << 3);
    const int b_col = ((lane >> 3) & 1) << 3;

    for (int t = 0; t < NCH; t++) {
        cp_wait1();
        __syncthreads();
        const uint32_t sA = sm0 + (t & 1) * STAGE_BYTES;
        const uint32_t aBase = sA + ch * (ROWS_CTA * 128);
        const uint32_t bBase = sA + B_OFF + matsel * (256 * 128);

#pragma unroll
        for (int kk = 0; kk < KC; kk += 16) {
            uint32_t a[2][4];
#pragma unroll
            for (int mf = 0; mf < 2; mf++) {
                int row = mf * 16 + a_row;
                ldsm4(a[mf], aBase + sw128((uint32_t)(row * 128 + (kk + a_col) * 2)));
            }
#pragma unroll
            for (int bi = 0; bi < 8; bi++) {
                int rowb = colh + bi * 16 + b_row;
                uint32_t b[4];
                ldsm4(b, bBase + sw128((uint32_t)(rowb * 128 + (kk + b_col) * 2)));
#pragma unroll
                for (int mf = 0; mf < 2; mf++) {
                    mma16816(acc[mf][bi * 2 + 0], a[mf], b[0], b[1]);
                    mma16816(acc[mf][bi * 2 + 1], a[mf], b[2], b[3]);
                }
            }
        }
        __syncthreads();

        int tn = t + 2;
        if (tn < NCH) {
            load_stage(sm0 + (tn & 1) * STAGE_BYTES, n0, tn * KC, tid, n_rows);
        }
        cp_commit();   // uniform group count
    }

    // ---------------- epilogue: assemble 32 x 1024 fp32 tile in smem ----------------
    float* sOut = (float*)dsm;          // 128 KB
#pragma unroll
    for (int mf = 0; mf < 2; mf++) {
#pragma unroll
        for (int nf = 0; nf < 16; nf++) {
            int c = colh + nf * 8 + 2 * (lane & 3);
            float* A = acc[mf][nf];
#pragma unroll
            for (int h = 0; h < 2; h++) {
                int row = mf * 16 + h * 8 + (lane >> 2);
                float v0 = A[2 * h + 0], v1 = A[2 * h + 1];
                if (ch == 0) {
                    sOut[row * 1024 + c]     = v0;
                    sOut[row * 1024 + c + 1] = v1;
                } else {
                    sOut[row * 1024 + 256 + 3 * c + (ch - 1)]       = v0;
                    sOut[row * 1024 + 256 + 3 * (c + 1) + (ch - 1)] = v1;
                }
            }
        }
    }
    __syncthreads();

    // coalesced copy out: 32 rows x 256 float4
#pragma unroll
    for (int j = 0; j < 32; j++) {
        int p = tid + j * 256;
        int row = p >> 8;
        int c4 = p & 255;
        if (n0 + row < n_rows) {
            const float* s = sOut + row * 1024 + c4 * 4;
            ((float4*)out)[(size_t)(n0 + row) * 256 + c4] =
                make_float4(s[0], s[1], s[2], s[3]);
        }
    }
}

// ---------------- launch ----------------
extern "C" void kernel_launch(void* const* d_in, const int* in_sizes, int n_in,
                              void* d_out, int out_size) {
    const float* x1   = (const float*)d_in[0];
    const float* x2   = (const float*)d_in[1];
    const float* w000 = (const float*)d_in[2];
    const float* w011 = (const float*)d_in[3];
    const float* w101 = (const float*)d_in[4];
    const float* w110 = (const float*)d_in[5];
    float* out = (float*)d_out;

    int n_rows = in_sizes[1] / 4;
    if (n_rows > NPAD) n_rows = NPAD;
    int row_tiles = (n_rows + ROWS_CTA - 1) / ROWS_CTA;

    prep_w_kernel<<<(2 * MULC * KTOT) / 256, 256>>>(w000, w011, w101, w110);
    prep_x_kernel<<<dim3(n_rows, 2), 256>>>(x1, x2, n_rows);

    cudaFuncSetAttribute(tp_gemm_kernel, cudaFuncAttributeMaxDynamicSharedMemorySize, SMEM_REQ);
    tp_gemm_kernel<<<row_tiles, 256, SMEM_REQ>>>(out, n_rows);
}

// round 9
// speedup vs baseline: 7.2680x; 1.1121x over previous
#include <cuda_runtime.h>
#include <cuda_fp16.h>
#include <cstdint>

#define MULC 256
#define KTOT 512
#define CINV 0.57735026918962576451f

// ---------------- scratch (no cudaMalloc allowed) ----------------
__device__ __align__(128) __half g_Wh[(size_t)2 * MULC * KTOT];   // Wt[mat][w][k]

__device__ __forceinline__ uint32_t smem_u32(const void* p) {
    uint32_t a;
    asm("{ .reg .u64 t; cvta.to.shared.u64 t, %1; cvt.u32.u64 %0, t; }"
        : "=r"(a) : "l"(p));
    return a;
}
__device__ __forceinline__ uint32_t sw128(uint32_t off) {
    return off ^ ((off >> 3) & 0x70u);
}

// ---------------- kernel: transpose weights -> fp16 Wt[mat][w][k] ----------------
// mat 0 = [W000 ; W110] along k, mat 1 = [W011 ; W101]
__global__ __launch_bounds__(256) void prep_w_kernel(const float* __restrict__ w000,
                                                     const float* __restrict__ w011,
                                                     const float* __restrict__ w101,
                                                     const float* __restrict__ w110) {
    int t = blockIdx.x * 256 + threadIdx.x;     // over 2*256*512
    int mat = t >> 17;
    int rem = t & 131071;
    int w = rem >> 9;
    int k = rem & 511;
    float v;
    if (mat == 0) v = (k < MULC) ? w000[(size_t)k * MULC + w] : w110[(size_t)(k - MULC) * MULC + w];
    else          v = (k < MULC) ? w011[(size_t)k * MULC + w] : w101[(size_t)(k - MULC) * MULC + w];
    g_Wh[t] = __float2half_rn(v);
}

// ---------------- fused GEMM: A computed on the fly ----------------
// CTA: 32 rows x 256 cols x 4 channels. K=512 in 8 chunks of 64, 2-stage pipeline.
// A channels: P0=[s1*s2 , c*(v1.v2)], P1+i=[c*s1*v2_i , c*v1_i*s2]
#define KC 64
#define NCH 8
#define ROWS_CTA 32
#define A_BYTES (4 * ROWS_CTA * 128)        // 16 KB  (4 channel A tiles)
#define B_OFF   A_BYTES
#define B_BYTES (512 * 128)                 // 64 KB  (both weight mats' k-slice)
#define STAGE_BYTES (A_BYTES + B_BYTES)     // 80 KB
#define SMEM_REQ (2 * STAGE_BYTES)          // 160 KB (also covers 128 KB epilogue tile)

__device__ __forceinline__ void cp16(uint32_t dst, const void* src) {
    asm volatile("cp.async.cg.shared.global [%0], [%1], 16;" :: "r"(dst), "l"(src) : "memory");
}
__device__ __forceinline__ void cp_commit() {
    asm volatile("cp.async.commit_group;" ::: "memory");
}
__device__ __forceinline__ void cp_wait1() {
    asm volatile("cp.async.wait_group 1;" ::: "memory");
}
__device__ __forceinline__ void ldsm4(uint32_t* r, uint32_t addr) {
    asm volatile("ldmatrix.sync.aligned.m8n8.x4.shared.b16 {%0,%1,%2,%3}, [%4];"
                 : "=r"(r[0]), "=r"(r[1]), "=r"(r[2]), "=r"(r[3]) : "r"(addr));
}
__device__ __forceinline__ void mma16816(float* c, const uint32_t* a, uint32_t b0, uint32_t b1) {
    asm volatile("mma.sync.aligned.m16n8k16.row.col.f32.f16.f16.f32 "
                 "{%0,%1,%2,%3}, {%4,%5,%6,%7}, {%8,%9}, {%0,%1,%2,%3};"
                 : "+f"(c[0]), "+f"(c[1]), "+f"(c[2]), "+f"(c[3])
                 : "r"(a[0]), "r"(a[1]), "r"(a[2]), "r"(a[3]), "r"(b0), "r"(b1));
}

__device__ __forceinline__ void load_B(uint32_t sbase, int k0, int tid) {
#pragma unroll
    for (int it = 0; it < 16; it++) {
        int p = tid + it * 256;
        int r = p >> 3, j = p & 7;          // r: 0..511 spans mat0 then mat1
        cp16(sbase + B_OFF + sw128((uint32_t)(r * 128 + j * 16)),
             g_Wh + (size_t)r * KTOT + k0 + j * 8);
    }
}

// Compute + store the A tile for chunk t into smem (swizzled fp16).
__device__ __forceinline__ void convert_A(char* abase, int t, int n0,
                                          const float* __restrict__ x1,
                                          const float4* s_sc, int tid, int n_rows) {
#pragma unroll
    for (int it = 0; it < 4; it++) {
        int p = tid + it * 256;
        int r = p >> 3, j = p & 7;          // r: ch = r>>5, row = r&31
        int ch = r >> 5;
        int row32 = r & 31;
        int n = n0 + row32;
        if (n >= n_rows) n = n_rows - 1;
        const float* xr = x1 + (size_t)n * (4 * MULC);
        float4 sc = s_sc[row32];            // {s2, c*w2x, c*w2y, c*w2z}
        __half h[8];
        if (t < 4) {
            // s-region: k = t*64 + j*8 + u
            const float* src = xr + t * KC + j * 8;
            float4 f0 = *(const float4*)(src);
            float4 f1 = *(const float4*)(src + 4);
            float fs[8] = {f0.x, f0.y, f0.z, f0.w, f1.x, f1.y, f1.z, f1.w};
            float scale = (ch == 0) ? sc.x : ((ch == 1) ? sc.y : ((ch == 2) ? sc.z : sc.w));
#pragma unroll
            for (int u = 0; u < 8; u++) h[u] = __float2half_rn(fs[u] * scale);
        } else {
            // v-region: kp = (t-4)*64 + j*8 + u ; v_i at xr[256 + 3*kp + i]
            int kq = (t - 4) * KC + j * 8;
            const float* base = xr + MULC + 3 * kq;
            if (ch == 0) {
                float4 fr[6];
#pragma unroll
                for (int q = 0; q < 6; q++) fr[q] = *(const float4*)(base + 4 * q);
                const float* f = (const float*)fr;
#pragma unroll
                for (int u = 0; u < 8; u++)
                    h[u] = __float2half_rn(f[3 * u] * sc.y + f[3 * u + 1] * sc.z +
                                           f[3 * u + 2] * sc.w);
            } else {
                int d = ch - 1;
                float cs2 = CINV * sc.x;
#pragma unroll
                for (int u = 0; u < 8; u++)
                    h[u] = __float2half_rn(base[3 * u + d] * cs2);
            }
        }
        uint32_t pk[4];
#pragma unroll
        for (int q = 0; q < 4; q++) {
            __half2 hh = __halves2half2(h[2 * q], h[2 * q + 1]);
            pk[q] = *(uint32_t*)&hh;
        }
        *(uint4*)(abase + sw128((uint32_t)(r * 128 + j * 16))) =
            make_uint4(pk[0], pk[1], pk[2], pk[3]);
    }
}

__global__ __launch_bounds__(256, 1) void tp_gemm_kernel(const float* __restrict__ x1,
                                                         const float* __restrict__ x2,
                                                         float* __restrict__ out,
                                                         int n_rows) {
    extern __shared__ __align__(1024) char dsm[];
    __shared__ float4 s_sc[ROWS_CTA];
    const uint32_t sm0 = smem_u32(dsm);

    const int tid = threadIdx.x;
    const int lane = tid & 31;
    const int wid = tid >> 5;
    const int ch = wid >> 1;            // channel 0..3
    const int colh = (wid & 1) * 128;   // col half within 256
    const int matsel = (ch == 0) ? 0 : 1;
    const int n0 = blockIdx.x * ROWS_CTA;

    // stage per-row x2 scale factors
    if (tid < ROWS_CTA) {
        int n = n0 + tid;
        if (n >= n_rows) n = n_rows - 1;
        float4 x = *(const float4*)(x2 + (size_t)n * 4);
        s_sc[tid] = make_float4(x.x, CINV * x.y, CINV * x.z, CINV * x.w);
    }
    __syncthreads();

    float acc[2][16][4];
#pragma unroll
    for (int mf = 0; mf < 2; mf++)
#pragma unroll
        for (int nf = 0; nf < 16; nf++)
#pragma unroll
            for (int q = 0; q < 4; q++)
                acc[mf][nf][q] = 0.0f;

    // prologue: stages 0,1
    load_B(sm0, 0, tid);
    cp_commit();
    convert_A(dsm, 0, n0, x1, s_sc, tid, n_rows);
    load_B(sm0 + STAGE_BYTES, KC, tid);
    cp_commit();
    convert_A(dsm + STAGE_BYTES, 1, n0, x1, s_sc, tid, n_rows);

    const int a_row = (lane & 15);
    const int a_col = (lane >> 4) << 3;
    const int b_row = (lane & 7) + ((lane >> 4) << 3);
    const int b_col = ((lane >> 3) & 1) << 3;

    for (int t = 0; t < NCH; t++) {
        cp_wait1();
        __syncthreads();
        const uint32_t sA = sm0 + (t & 1) * STAGE_BYTES;
        const uint32_t aBase = sA + ch * (ROWS_CTA * 128);
        const uint32_t bBase = sA + B_OFF + matsel * (256 * 128);

#pragma unroll
        for (int kk = 0; kk < KC; kk += 16) {
            uint32_t a[2][4];
#pragma unroll
            for (int mf = 0; mf < 2; mf++) {
                int row = mf * 16 + a_row;
                ldsm4(a[mf], aBase + sw128((uint32_t)(row * 128 + (kk + a_col) * 2)));
            }
#pragma unroll
            for (int bi = 0; bi < 8; bi++) {
                int rowb = colh + bi * 16 + b_row;
                uint32_t b[4];
                ldsm4(b, bBase + sw128((uint32_t)(rowb * 128 + (kk + b_col) * 2)));
#pragma unroll
                for (int mf = 0; mf < 2; mf++) {
                    mma16816(acc[mf][bi * 2 + 0], a[mf], b[0], b[1]);
                    mma16816(acc[mf][bi * 2 + 1], a[mf], b[2], b[3]);
                }
            }
        }
        __syncthreads();

        int tn = t + 2;
        if (tn < NCH) {
            load_B(sm0 + (tn & 1) * STAGE_BYTES, tn * KC, tid);
        }
        cp_commit();   // uniform group count
        if (tn < NCH) {
            convert_A(dsm + (tn & 1) * STAGE_BYTES, tn, n0, x1, s_sc, tid, n_rows);
        }
    }

    // ---------------- epilogue: assemble 32 x 1024 fp32 tile in smem ----------------
    float* sOut = (float*)dsm;          // 128 KB
#pragma unroll
    for (int mf = 0; mf < 2; mf++) {
#pragma unroll
        for (int nf = 0; nf < 16; nf++) {
            int c = colh + nf * 8 + 2 * (lane & 3);
            float* A = acc[mf][nf];
#pragma unroll
            for (int h = 0; h < 2; h++) {
                int row = mf * 16 + h * 8 + (lane >> 2);
                float v0 = A[2 * h + 0], v1 = A[2 * h + 1];
                if (ch == 0) {
                    sOut[row * 1024 + c]     = v0;
                    sOut[row * 1024 + c + 1] = v1;
                } else {
                    sOut[row * 1024 + 256 + 3 * c + (ch - 1)]       = v0;
                    sOut[row * 1024 + 256 + 3 * (c + 1) + (ch - 1)] = v1;
                }
            }
        }
    }
    __syncthreads();

    // coalesced copy out: 32 rows x 256 float4
#pragma unroll
    for (int j = 0; j < 32; j++) {
        int p = tid + j * 256;
        int row = p >> 8;
        int c4 = p & 255;
        if (n0 + row < n_rows) {
            const float* s = sOut + row * 1024 + c4 * 4;
            ((float4*)out)[(size_t)(n0 + row) * 256 + c4] =
                make_float4(s[0], s[1], s[2], s[3]);
        }
    }
}

// ---------------- launch ----------------
extern "C" void kernel_launch(void* const* d_in, const int* in_sizes, int n_in,
                              void* d_out, int out_size) {
    const float* x1   = (const float*)d_in[0];
    const float* x2   = (const float*)d_in[1];
    const float* w000 = (const float*)d_in[2];
    const float* w011 = (const float*)d_in[3];
    const float* w101 = (const float*)d_in[4];
    const float* w110 = (const float*)d_in[5];
    float* out = (float*)d_out;

    int n_rows = in_sizes[1] / 4;
    int row_tiles = (n_rows + ROWS_CTA - 1) / ROWS_CTA;

    prep_w_kernel<<<(2 * MULC * KTOT) / 256, 256>>>(w000, w011, w101, w110);

    cudaFuncSetAttribute(tp_gemm_kernel, cudaFuncAttributeMaxDynamicSharedMemorySize, SMEM_REQ);
    tp_gemm_kernel<<<row_tiles, 256, SMEM_REQ>>>(x1, x2, out, n_rows);
}

// round 10
// speedup vs baseline: 7.6327x; 1.0502x over previous
#include <cuda_runtime.h>
#include <cuda_fp16.h>
#include <cstdint>

#define MULC 256
#define KTOT 512
#define CINV 0.57735026918962576451f

// ---------------- scratch (no cudaMalloc allowed) ----------------
__device__ __align__(128) __half g_Wh[(size_t)2 * MULC * KTOT];   // Wt[mat][w][k]

__device__ __forceinline__ uint32_t smem_u32(const void* p) {
    uint32_t a;
    asm("{ .reg .u64 t; cvta.to.shared.u64 t, %1; cvt.u32.u64 %0, t; }"
        : "=r"(a) : "l"(p));
    return a;
}
__device__ __forceinline__ uint32_t sw128(uint32_t off) {
    return off ^ ((off >> 3) & 0x70u);
}

// ---------------- kernel: transpose weights -> fp16 Wt[mat][w][k] ----------------
// mat 0 = [W000 ; W110] along k, mat 1 = [W011 ; W101]
__global__ __launch_bounds__(256) void prep_w_kernel(const float* __restrict__ w000,
                                                     const float* __restrict__ w011,
                                                     const float* __restrict__ w101,
                                                     const float* __restrict__ w110) {
    int t = blockIdx.x * 256 + threadIdx.x;     // over 2*256*512
    int mat = t >> 17;
    int rem = t & 131071;
    int w = rem >> 9;
    int k = rem & 511;
    float v;
    if (mat == 0) v = (k < MULC) ? w000[(size_t)k * MULC + w] : w110[(size_t)(k - MULC) * MULC + w];
    else          v = (k < MULC) ? w011[(size_t)k * MULC + w] : w101[(size_t)(k - MULC) * MULC + w];
    g_Wh[t] = __float2half_rn(v);
}

// ---------------- fused GEMM: A on the fly, 2 CTAs/SM ----------------
// CTA: 32 rows x 128 cols x 4 channels. K=512 in 8 chunks of 64, 2-stage pipeline.
#define KC 64
#define NCH 8
#define ROWS_CTA 32
#define COLS_CTA 128
#define A_BYTES (4 * ROWS_CTA * 128)        // 16 KB (4 channel A tiles)
#define B_OFF   A_BYTES
#define B_BYTES (256 * 128)                 // 32 KB (col-half of both mats)
#define STAGE_BYTES (A_BYTES + B_BYTES)     // 48 KB
#define SMEM_REQ (2 * STAGE_BYTES)          // 96 KB (covers 64 KB epilogue tile)

__device__ __forceinline__ void cp16(uint32_t dst, const void* src) {
    asm volatile("cp.async.cg.shared.global [%0], [%1], 16;" :: "r"(dst), "l"(src) : "memory");
}
__device__ __forceinline__ void cp_commit() {
    asm volatile("cp.async.commit_group;" ::: "memory");
}
__device__ __forceinline__ void cp_wait1() {
    asm volatile("cp.async.wait_group 1;" ::: "memory");
}
__device__ __forceinline__ void ldsm4(uint32_t* r, uint32_t addr) {
    asm volatile("ldmatrix.sync.aligned.m8n8.x4.shared.b16 {%0,%1,%2,%3}, [%4];"
                 : "=r"(r[0]), "=r"(r[1]), "=r"(r[2]), "=r"(r[3]) : "r"(addr));
}
__device__ __forceinline__ void mma16816(float* c, const uint32_t* a, uint32_t b0, uint32_t b1) {
    asm volatile("mma.sync.aligned.m16n8k16.row.col.f32.f16.f16.f32 "
                 "{%0,%1,%2,%3}, {%4,%5,%6,%7}, {%8,%9}, {%0,%1,%2,%3};"
                 : "+f"(c[0]), "+f"(c[1]), "+f"(c[2]), "+f"(c[3])
                 : "r"(a[0]), "r"(a[1]), "r"(a[2]), "r"(a[3]), "r"(b0), "r"(b1));
}

// B: 256 smem rows = mat0 cols [c0,c0+128) then mat1 cols [c0,c0+128)
__device__ __forceinline__ void load_B(uint32_t sbase, int c0, int k0, int tid) {
#pragma unroll
    for (int it = 0; it < 8; it++) {
        int p = tid + it * 256;
        int r = p >> 3, j = p & 7;          // r: 0..255
        int grow = (r >> 7) * MULC + c0 + (r & 127);
        cp16(sbase + B_OFF + sw128((uint32_t)(r * 128 + j * 16)),
             g_Wh + (size_t)grow * KTOT + k0 + j * 8);
    }
}

// Compute + store the A tile for chunk t into smem (swizzled fp16).
// Channels: P0=[s1*s2 , c*(v1.v2)], P1+i=[c*s1*v2_i , c*v1_i*s2]
__device__ __forceinline__ void convert_A(char* abase, int t, int n0,
                                          const float* __restrict__ x1,
                                          const float4* s_sc, int tid, int n_rows) {
#pragma unroll
    for (int it = 0; it < 4; it++) {
        int p = tid + it * 256;
        int r = p >> 3, j = p & 7;          // r: ch = r>>5, row = r&31
        int ch = r >> 5;
        int row32 = r & 31;
        int n = n0 + row32;
        if (n >= n_rows) n = n_rows - 1;
        const float* xr = x1 + (size_t)n * (4 * MULC);
        float4 sc = s_sc[row32];            // {s2, c*w2x, c*w2y, c*w2z}
        __half h[8];
        if (t < 4) {
            const float* src = xr + t * KC + j * 8;
            float4 f0 = *(const float4*)(src);
            float4 f1 = *(const float4*)(src + 4);
            float fs[8] = {f0.x, f0.y, f0.z, f0.w, f1.x, f1.y, f1.z, f1.w};
            float scale = (ch == 0) ? sc.x : ((ch == 1) ? sc.y : ((ch == 2) ? sc.z : sc.w));
#pragma unroll
            for (int u = 0; u < 8; u++) h[u] = __float2half_rn(fs[u] * scale);
        } else {
            int kq = (t - 4) * KC + j * 8;
            const float* base = xr + MULC + 3 * kq;
            if (ch == 0) {
                float4 fr[6];
#pragma unroll
                for (int q = 0; q < 6; q++) fr[q] = *(const float4*)(base + 4 * q);
                const float* f = (const float*)fr;
#pragma unroll
                for (int u = 0; u < 8; u++)
                    h[u] = __float2half_rn(f[3 * u] * sc.y + f[3 * u + 1] * sc.z +
                                           f[3 * u + 2] * sc.w);
            } else {
                int d = ch - 1;
                float cs2 = CINV * sc.x;
#pragma unroll
                for (int u = 0; u < 8; u++)
                    h[u] = __float2half_rn(base[3 * u + d] * cs2);
            }
        }
        uint32_t pk[4];
#pragma unroll
        for (int q = 0; q < 4; q++) {
            __half2 hh = __halves2half2(h[2 * q], h[2 * q + 1]);
            pk[q] = *(uint32_t*)&hh;
        }
        *(uint4*)(abase + sw128((uint32_t)(r * 128 + j * 16))) =
            make_uint4(pk[0], pk[1], pk[2], pk[3]);
    }
}

__global__ __launch_bounds__(256, 2) void tp_gemm_kernel(const float* __restrict__ x1,
                                                         const float* __restrict__ x2,
                                                         float* __restrict__ out,
                                                         int n_rows) {
    extern __shared__ __align__(1024) char dsm[];
    __shared__ float4 s_sc[ROWS_CTA];
    const uint32_t sm0 = smem_u32(dsm);

    const int tid = threadIdx.x;
    const int lane = tid & 31;
    const int wid = tid >> 5;
    const int ch = wid >> 1;            // channel 0..3
    const int colq = (wid & 1) * 64;    // 64-col half within the CTA's 128 cols
    const int matsel = (ch == 0) ? 0 : 1;
    const int n0 = blockIdx.x * ROWS_CTA;
    const int c0 = blockIdx.y * COLS_CTA;   // 0 or 128

    if (tid < ROWS_CTA) {
        int n = n0 + tid;
        if (n >= n_rows) n = n_rows - 1;
        float4 x = *(const float4*)(x2 + (size_t)n * 4);
        s_sc[tid] = make_float4(x.x, CINV * x.y, CINV * x.z, CINV * x.w);
    }
    __syncthreads();

    float acc[2][8][4];
#pragma unroll
    for (int mf = 0; mf < 2; mf++)
#pragma unroll
        for (int nf = 0; nf < 8; nf++)
#pragma unroll
            for (int q = 0; q < 4; q++)
                acc[mf][nf][q] = 0.0f;

    // prologue: stages 0,1
    load_B(sm0, c0, 0, tid);
    cp_commit();
    convert_A(dsm, 0, n0, x1, s_sc, tid, n_rows);
    load_B(sm0 + STAGE_BYTES, c0, KC, tid);
    cp_commit();
    convert_A(dsm + STAGE_BYTES, 1, n0, x1, s_sc, tid, n_rows);

    const int a_row = (lane & 15);
    const int a_col = (lane >> 4) << 3;
    const int b_row = (lane & 7) + ((lane >> 4) << 3);
    const int b_col = ((lane >> 3) & 1) << 3;

    for (int t = 0; t < NCH; t++) {
        cp_wait1();
        __syncthreads();
        const uint32_t sA = sm0 + (t & 1) * STAGE_BYTES;
        const uint32_t aBase = sA + ch * (ROWS_CTA * 128);
        const uint32_t bBase = sA + B_OFF + matsel * (128 * 128);

#pragma unroll
        for (int kk = 0; kk < KC; kk += 16) {
            uint32_t a[2][4];
#pragma unroll
            for (int mf = 0; mf < 2; mf++) {
                int row = mf * 16 + a_row;
                ldsm4(a[mf], aBase + sw128((uint32_t)(row * 128 + (kk + a_col) * 2)));
            }
#pragma unroll
            for (int bi = 0; bi < 4; bi++) {
                int rowb = colq + bi * 16 + b_row;
                uint32_t b[4];
                ldsm4(b, bBase + sw128((uint32_t)(rowb * 128 + (kk + b_col) * 2)));
#pragma unroll
                for (int mf = 0; mf < 2; mf++) {
                    mma16816(acc[mf][bi * 2 + 0], a[mf], b[0], b[1]);
                    mma16816(acc[mf][bi * 2 + 1], a[mf], b[2], b[3]);
                }
            }
        }
        __syncthreads();

        int tn = t + 2;
        if (tn < NCH) {
            load_B(sm0 + (tn & 1) * STAGE_BYTES, c0, tn * KC, tid);
        }
        cp_commit();   // uniform group count
        if (tn < NCH) {
            convert_A(dsm + (tn & 1) * STAGE_BYTES, tn, n0, x1, s_sc, tid, n_rows);
        }
    }

    // ---------------- epilogue: assemble 32 x 512 fp32 tile in smem ----------------
    // layout per row: [0,128)   -> out0 cols [c0, c0+128)
    //                 [128,512) -> out1 block [256+3*c0, 256+3*c0+384)
    float* sOut = (float*)dsm;          // 64 KB
#pragma unroll
    for (int mf = 0; mf < 2; mf++) {
#pragma unroll
        for (int nf = 0; nf < 8; nf++) {
            int c = colq + nf * 8 + 2 * (lane & 3);   // 0..127 local col
            float* A = acc[mf][nf];
#pragma unroll
            for (int h = 0; h < 2; h++) {
                int row = mf * 16 + h * 8 + (lane >> 2);
                float v0 = A[2 * h + 0], v1 = A[2 * h + 1];
                if (ch == 0) {
                    sOut[row * 512 + c]     = v0;
                    sOut[row * 512 + c + 1] = v1;
                } else {
                    sOut[row * 512 + 128 + 3 * c + (ch - 1)]       = v0;
                    sOut[row * 512 + 128 + 3 * (c + 1) + (ch - 1)] = v1;
                }
            }
        }
    }
    __syncthreads();

    // coalesced copy out: 32 rows x 128 float4
#pragma unroll
    for (int j = 0; j < 16; j++) {
        int p = tid + j * 256;
        int row = p >> 7;
        int c4 = p & 127;
        int n = n0 + row;
        if (n < n_rows) {
            const float* s = sOut + row * 512 + c4 * 4;
            float4 v = make_float4(s[0], s[1], s[2], s[3]);
            size_t gf = (c4 < 32) ? ((size_t)n * 1024 + c0 + c4 * 4)
                                  : ((size_t)n * 1024 + 256 + 3 * c0 + (c4 - 32) * 4);
            *(float4*)(out + gf) = v;
        }
    }
}

// ---------------- launch ----------------
extern "C" void kernel_launch(void* const* d_in, const int* in_sizes, int n_in,
                              void* d_out, int out_size) {
    const float* x1   = (const float*)d_in[0];
    const float* x2   = (const float*)d_in[1];
    const float* w000 = (const float*)d_in[2];
    const float* w011 = (const float*)d_in[3];
    const float* w101 = (const float*)d_in[4];
    const float* w110 = (const float*)d_in[5];
    float* out = (float*)d_out;

    int n_rows = in_sizes[1] / 4;
    int row_tiles = (n_rows + ROWS_CTA - 1) / ROWS_CTA;

    prep_w_kernel<<<(2 * MULC * KTOT) / 256, 256>>>(w000, w011, w101, w110);

    cudaFuncSetAttribute(tp_gemm_kernel, cudaFuncAttributeMaxDynamicSharedMemorySize, SMEM_REQ);
    tp_gemm_kernel<<<dim3(row_tiles, 2), 256, SMEM_REQ>>>(x1, x2, out, n_rows);
}